// round 7
// baseline (speedup 1.0000x reference)
#include <cuda_runtime.h>
#include <cuda_bf16.h>
#include <math_constants.h>
#include <cstdint>
#include <mma.h>

using namespace nvcuda;

#define N_NODES 50000
#define N_EDGES 600000
#define N_REL   64
#define DIM     128
#define DIM4    32

#define SCAN_B 1024
#define SCAN_G ((N_NODES + SCAN_B - 1) / SCAN_B)   // 49

typedef unsigned long long ull;

// ---------------- device scratch (no allocations allowed) ----------------
__device__ float g_prev[N_NODES * DIM];
__device__ __nv_bfloat16 g_ah[N_NODES * DIM];   // A (prev) bf16 hi
__device__ __nv_bfloat16 g_al[N_NODES * DIM];   // A (prev) bf16 lo
__device__ __nv_bfloat16 g_nh[N_NODES * DIM];   // neigh bf16 hi
__device__ __nv_bfloat16 g_nl[N_NODES * DIM];   // neigh bf16 lo
__device__ int   g_deg[N_NODES];
__device__ int   g_cursor[N_NODES];
__device__ int   g_rowptr[N_NODES + 1];
__device__ int   g_part[SCAN_G];
__device__ int   g_nbr[N_EDGES];
__device__ int   g_rel[N_EDGES];
// W split: [layer][k-chunk] -> 64KB blob: 32KB hi (128x128 bf16 [k][n]) + 32KB lo
__device__ __align__(16) unsigned char g_Wsw[2][2][65536];

__device__ __forceinline__ float tanh_fast(float x) {
    float y; asm("tanh.approx.f32 %0, %1;" : "=f"(y) : "f"(x)); return y;
}
__device__ __forceinline__ ull pack4_hi(float4 v, float4& rem) {
    __nv_bfloat16 h0 = __float2bfloat16(v.x);
    __nv_bfloat16 h1 = __float2bfloat16(v.y);
    __nv_bfloat16 h2 = __float2bfloat16(v.z);
    __nv_bfloat16 h3 = __float2bfloat16(v.w);
    rem.x = v.x - __bfloat162float(h0);
    rem.y = v.y - __bfloat162float(h1);
    rem.z = v.z - __bfloat162float(h2);
    rem.w = v.w - __bfloat162float(h3);
    return (ull)__bfloat16_as_ushort(h0)
         | ((ull)__bfloat16_as_ushort(h1) << 16)
         | ((ull)__bfloat16_as_ushort(h2) << 32)
         | ((ull)__bfloat16_as_ushort(h3) << 48);
}
__device__ __forceinline__ ull pack4(float4 v) {
    return (ull)__bfloat16_as_ushort(__float2bfloat16(v.x))
         | ((ull)__bfloat16_as_ushort(__float2bfloat16(v.y)) << 16)
         | ((ull)__bfloat16_as_ushort(__float2bfloat16(v.z)) << 32)
         | ((ull)__bfloat16_as_ushort(__float2bfloat16(v.w)) << 48);
}

// ---------------- CSR build ----------------
__global__ void k_zero()
{
    int i = blockIdx.x * blockDim.x + threadIdx.x;
    if (i < N_NODES) { g_deg[i] = 0; g_cursor[i] = 0; }
}
__global__ void k_count(const int* __restrict__ dst)
{
    int e = blockIdx.x * blockDim.x + threadIdx.x;
    if (e < N_EDGES) atomicAdd(&g_deg[dst[e]], 1);
}
__global__ void k_scan1()
{
    __shared__ int warpsum[32];
    const int lane = threadIdx.x & 31;
    const int wid  = threadIdx.x >> 5;
    const int i    = blockIdx.x * SCAN_B + threadIdx.x;

    int v = (i < N_NODES) ? g_deg[i] : 0;
    int s = v;
    #pragma unroll
    for (int o = 1; o < 32; o <<= 1) {
        int u = __shfl_up_sync(0xffffffffu, s, o);
        if (lane >= o) s += u;
    }
    if (lane == 31) warpsum[wid] = s;
    __syncthreads();
    if (wid == 0) {
        int ws = warpsum[lane];
        #pragma unroll
        for (int o = 1; o < 32; o <<= 1) {
            int u = __shfl_up_sync(0xffffffffu, ws, o);
            if (lane >= o) ws += u;
        }
        warpsum[lane] = ws;
    }
    __syncthreads();
    int incl = s + (wid ? warpsum[wid - 1] : 0);
    if (i < N_NODES) g_rowptr[i] = incl - v;
    if (threadIdx.x == SCAN_B - 1) g_part[blockIdx.x] = incl;
}
__global__ void k_scan2()
{
    __shared__ int sp[64];
    const int t = threadIdx.x;
    sp[t] = (t < SCAN_G) ? g_part[t] : 0;
    __syncthreads();
    #pragma unroll
    for (int o = 1; o < 64; o <<= 1) {
        int u = (t >= o) ? sp[t - o] : 0;
        __syncthreads();
        sp[t] += u;
        __syncthreads();
    }
    if (t < SCAN_G) g_part[t] = (t == 0) ? 0 : sp[t - 1];
    if (t == 63) g_rowptr[N_NODES] = sp[SCAN_G - 1];
}
__global__ void k_scan3()
{
    int i = blockIdx.x * SCAN_B + threadIdx.x;
    if (i < N_NODES) g_rowptr[i] += g_part[blockIdx.x];
}
__global__ void k_scatter(const int* __restrict__ dst,
                          const int* __restrict__ nbr,
                          const int* __restrict__ rel)
{
    int e = blockIdx.x * blockDim.x + threadIdx.x;
    if (e < N_EDGES) {
        int d   = dst[e];
        int pos = g_rowptr[d] + atomicAdd(&g_cursor[d], 1);
        g_nbr[pos] = nbr[e];
        g_rel[pos] = rel[e];
    }
}

// ---------------- W bf16 hi/lo split (once). blob[kc]: hi[k][n], lo[k][n] ----
__global__ void k_wconv(const float* __restrict__ W)
{
    int idx = blockIdx.x * blockDim.x + threadIdx.x;  // 65536
    if (idx >= 2 * 2 * 128 * 128) return;
    int l  = idx >> 15;
    int r  = idx & 32767;
    int kc = r >> 14; r &= 16383;
    int k  = r >> 7;
    int n  = r & 127;
    float w = W[(l * 256 + kc * 128 + k) * 128 + n];
    __nv_bfloat16 hi = __float2bfloat16(w);
    __nv_bfloat16 lo = __float2bfloat16(w - __bfloat162float(hi));
    __nv_bfloat16* base = (__nv_bfloat16*)&g_Wsw[l][kc][0];
    base[k * 128 + n]         = hi;
    base[16384 + k * 128 + n] = lo;
}

// ---------------- entity -> bf16 hi/lo split (once, feeds layer-0 A) ------
__global__ void k_esplit(const float* __restrict__ entity)
{
    int i = blockIdx.x * blockDim.x + threadIdx.x;    // float4 index
    if (i >= N_NODES * DIM4) return;
    float4 v = ((const float4*)entity)[i];
    float4 rem;
    ull ph = pack4_hi(v, rem);
    ((ull*)g_ah)[i] = ph;
    ((ull*)g_al)[i] = pack4(rem);
}

// ---------------- attention: one warp per node, writes bf16 hi/lo neigh ---
__global__ void __launch_bounds__(256)
k_attn(const float* __restrict__ in,
       const float* __restrict__ entity,
       const float* __restrict__ relation)
{
    const int wid  = threadIdx.x >> 5;
    const int lane = threadIdx.x & 31;
    const int node = blockIdx.x * 8 + wid;
    if (node >= N_NODES) return;

    const int start = g_rowptr[node];
    const int end   = g_rowptr[node + 1];
    if (start == end) return;                         // epilogue handles deg==0

    const float4* ent4 = (const float4*)entity;
    const float4* in4  = (const float4*)in;
    const float4* rel4 = (const float4*)relation;

    float4 ed = ent4[node * DIM4 + lane];

    float  m    = -CUDART_INF_F;
    float  dsum = 0.f;
    float4 acc  = make_float4(0.f, 0.f, 0.f, 0.f);

    int nb = g_nbr[start];
    int rl = g_rel[start];
    float4 x = in4[nb * DIM4 + lane];
    float4 r = rel4[rl * DIM4 + lane];

    for (int e = start; e < end; ++e) {
        float4 xc = x, rc = r;
        if (e + 1 < end) {
            int nb2 = g_nbr[e + 1];
            int rl2 = g_rel[e + 1];
            x = in4[nb2 * DIM4 + lane];
            r = rel4[rl2 * DIM4 + lane];
        }
        float4 q;
        q.x = tanh_fast(ed.x + rc.x);
        q.y = tanh_fast(ed.y + rc.y);
        q.z = tanh_fast(ed.z + rc.z);
        q.w = tanh_fast(ed.w + rc.w);

        float s = xc.x * q.x + xc.y * q.y + xc.z * q.z + xc.w * q.w;
        #pragma unroll
        for (int off = 16; off; off >>= 1)
            s += __shfl_xor_sync(0xffffffffu, s, off);

        if (s > m) {
            float sc = __expf(m - s);
            acc.x *= sc; acc.y *= sc; acc.z *= sc; acc.w *= sc;
            dsum  *= sc;
            m = s;
        }
        float w = __expf(s - m);
        dsum += w;
        acc.x += w * xc.x; acc.y += w * xc.y; acc.z += w * xc.z; acc.w += w * xc.w;
    }

    const float inv = 1.0f / dsum;
    float4 ng = make_float4(acc.x * inv, acc.y * inv, acc.z * inv, acc.w * inv);
    float4 rem;
    ull ph = pack4_hi(ng, rem);
    ((ull*)g_nh)[node * DIM4 + lane] = ph;
    ((ull*)g_nl)[node * DIM4 + lane] = pack4(rem);
}

// ---------------- WMMA bf16x3 GEMM + epilogue ----------------
// per block: 128 nodes x 128 cols; K=256 in two 128-chunks (A-split, neigh-split)
// A and B tiles byte-copied into padded smem (pre-split bf16, no converts).
// D += Ahi*Bhi + Ahi*Blo + Alo*Bhi  (f32 accumulate)
#define AS_STRIDE 136                       // bf16 elems per row (pad 8)
#define CS_STRIDE 132                       // f32 elems per row (pad 4)
#define SM_BIAS   0
#define SM_A_HI   1024
#define SM_A_LO   (SM_A_HI + 128 * AS_STRIDE * 2)
#define SM_B_HI   (SM_A_LO + 128 * AS_STRIDE * 2)
#define SM_B_LO   (SM_B_HI + 128 * AS_STRIDE * 2)
#define SM_C      1024                      // reuses A region after MMA
#define SMEM_TOTAL (SM_B_LO + 128 * AS_STRIDE * 2)   // 140288

__global__ void __launch_bounds__(256)
k_mma(const __nv_bfloat16* __restrict__ a_hi,
      const __nv_bfloat16* __restrict__ a_lo,
      const __nv_bfloat16* __restrict__ n_hi,
      const __nv_bfloat16* __restrict__ n_lo,
      const unsigned char* __restrict__ wsw,   // g_Wsw[layer]: 2 x 64KB blobs
      const float* __restrict__ bl,
      const float* __restrict__ entity,
      float*       __restrict__ out,
      __nv_bfloat16* __restrict__ w_hi,        // next-layer A split (or null)
      __nv_bfloat16* __restrict__ w_lo)
{
    extern __shared__ unsigned char smem[];
    const int t      = threadIdx.x;
    const int wid    = t >> 5;
    const int warp_m = wid >> 2;
    const int warp_n = wid & 3;
    const int m0     = blockIdx.x * 128;

    float* sbias = (float*)(smem + SM_BIAS);
    if (t < 128) sbias[t] = bl[t];

    __nv_bfloat16* Ah = (__nv_bfloat16*)(smem + SM_A_HI);
    __nv_bfloat16* Al = (__nv_bfloat16*)(smem + SM_A_LO);
    __nv_bfloat16* Bh = (__nv_bfloat16*)(smem + SM_B_HI);
    __nv_bfloat16* Bl = (__nv_bfloat16*)(smem + SM_B_LO);

    wmma::fragment<wmma::accumulator, 16, 16, 16, float> c[4][2];
    #pragma unroll
    for (int mt = 0; mt < 4; ++mt)
        #pragma unroll
        for (int nt = 0; nt < 2; ++nt)
            wmma::fill_fragment(c[mt][nt], 0.f);

    for (int kc = 0; kc < 2; ++kc) {
        const uint4* sah = (const uint4*)(kc ? n_hi : a_hi);
        const uint4* sal = (const uint4*)(kc ? n_lo : a_lo);
        __syncthreads();

        // A tiles: byte-copy pre-split bf16 [128 x 128] into padded smem
        #pragma unroll
        for (int p = 0; p < 8; ++p) {
            int idx = p * 256 + t;           // 2048 uint4 per tile
            int row = idx >> 4;
            int q   = idx & 15;              // 8-bf16 group
            int node = m0 + row;
            uint4 vh = make_uint4(0, 0, 0, 0), vl = make_uint4(0, 0, 0, 0);
            if (node < N_NODES) {
                vh = sah[node * 16 + q];
                vl = sal[node * 16 + q];
            }
            int eo = row * AS_STRIDE + q * 8;
            *(uint4*)(Ah + eo) = vh;
            *(uint4*)(Al + eo) = vl;
        }
        // B tiles: copy pre-split W blob into padded smem
        {
            const uint4* sh = (const uint4*)(wsw + kc * 65536);
            const uint4* sl = (const uint4*)(wsw + kc * 65536 + 32768);
            #pragma unroll
            for (int p = 0; p < 8; ++p) {
                int idx = p * 256 + t;       // 2048 uint4 per tile
                int row = idx >> 4;
                int q   = idx & 15;
                int eo  = row * AS_STRIDE + q * 8;
                *(uint4*)(Bh + eo) = sh[idx];
                *(uint4*)(Bl + eo) = sl[idx];
            }
        }
        __syncthreads();

        #pragma unroll
        for (int ks = 0; ks < 8; ++ks) {
            wmma::fragment<wmma::matrix_b, 16, 16, 16, __nv_bfloat16,
                           wmma::row_major> bh[2], blo[2];
            #pragma unroll
            for (int nt = 0; nt < 2; ++nt) {
                int ncol = warp_n * 32 + nt * 16;
                wmma::load_matrix_sync(bh[nt],  Bh + ks * 16 * AS_STRIDE + ncol,
                                       AS_STRIDE);
                wmma::load_matrix_sync(blo[nt], Bl + ks * 16 * AS_STRIDE + ncol,
                                       AS_STRIDE);
            }
            #pragma unroll
            for (int mt = 0; mt < 4; ++mt) {
                int mrow = warp_m * 64 + mt * 16;
                wmma::fragment<wmma::matrix_a, 16, 16, 16, __nv_bfloat16,
                               wmma::row_major> ah, alo;
                wmma::load_matrix_sync(ah,  Ah + mrow * AS_STRIDE + ks * 16,
                                       AS_STRIDE);
                wmma::load_matrix_sync(alo, Al + mrow * AS_STRIDE + ks * 16,
                                       AS_STRIDE);
                #pragma unroll
                for (int nt = 0; nt < 2; ++nt) {
                    wmma::mma_sync(c[mt][nt], ah,  bh[nt],  c[mt][nt]);
                    wmma::mma_sync(c[mt][nt], ah,  blo[nt], c[mt][nt]);
                    wmma::mma_sync(c[mt][nt], alo, bh[nt],  c[mt][nt]);
                }
            }
        }
    }
    __syncthreads();

    float* Cs = (float*)(smem + SM_C);
    #pragma unroll
    for (int mt = 0; mt < 4; ++mt)
        #pragma unroll
        for (int nt = 0; nt < 2; ++nt)
            wmma::store_matrix_sync(Cs + (warp_m * 64 + mt * 16) * CS_STRIDE
                                       + warp_n * 32 + nt * 16,
                                    c[mt][nt], CS_STRIDE, wmma::mem_row_major);
    __syncthreads();

    // epilogue: 2 threads per row: bias + leaky + L2 norm + deg-0 + A-split out
    {
        const int r    = t >> 1;
        const int half = t & 1;
        const int node = m0 + r;
        const float* crow = Cs + r * CS_STRIDE + half * 64;
        const float* brow = sbias + half * 64;

        float sq = 0.f;
        #pragma unroll
        for (int j = 0; j < 64; ++j) {
            float v = crow[j] + brow[j];
            v = (v > 0.f) ? v : 0.01f * v;
            sq += v * v;
        }
        sq += __shfl_xor_sync(0xffffffffu, sq, 1);
        float rn = rsqrtf(sq);

        if (node < N_NODES) {
            int deg = g_rowptr[node + 1] - g_rowptr[node];
            float4*       out4 = (float4*)out;
            const float4* ent4 = (const float4*)entity;
            #pragma unroll
            for (int j4 = 0; j4 < 16; ++j4) {
                float4 o;
                if (deg == 0) {
                    o = ent4[node * DIM4 + half * 16 + j4];
                } else {
                    float v0 = crow[j4 * 4 + 0] + brow[j4 * 4 + 0];
                    float v1 = crow[j4 * 4 + 1] + brow[j4 * 4 + 1];
                    float v2 = crow[j4 * 4 + 2] + brow[j4 * 4 + 2];
                    float v3 = crow[j4 * 4 + 3] + brow[j4 * 4 + 3];
                    o.x = ((v0 > 0.f) ? v0 : 0.01f * v0) * rn;
                    o.y = ((v1 > 0.f) ? v1 : 0.01f * v1) * rn;
                    o.z = ((v2 > 0.f) ? v2 : 0.01f * v2) * rn;
                    o.w = ((v3 > 0.f) ? v3 : 0.01f * v3) * rn;
                }
                out4[node * DIM4 + half * 16 + j4] = o;
                if (w_hi) {
                    float4 rem;
                    ull ph = pack4_hi(o, rem);
                    ((ull*)w_hi)[node * DIM4 + half * 16 + j4] = ph;
                    ((ull*)w_lo)[node * DIM4 + half * 16 + j4] = pack4(rem);
                }
            }
        }
    }
}

// ---------------- launch ----------------
extern "C" void kernel_launch(void* const* d_in, const int* in_sizes, int n_in,
                              void* d_out, int out_size)
{
    const float* entity   = (const float*)d_in[0];
    const float* relation = (const float*)d_in[1];
    const float* W        = (const float*)d_in[2];
    const float* b        = (const float*)d_in[3];
    const int*   edst     = (const int*)d_in[4];
    const int*   enbr     = (const int*)d_in[5];
    const int*   erel     = (const int*)d_in[6];
    float*       out      = (float*)d_out;

    float* prev = nullptr;
    __nv_bfloat16 *ah = nullptr, *al = nullptr, *nh = nullptr, *nl = nullptr;
    unsigned char* wsw = nullptr;
    cudaGetSymbolAddress((void**)&prev, g_prev);
    cudaGetSymbolAddress((void**)&ah,   g_ah);
    cudaGetSymbolAddress((void**)&al,   g_al);
    cudaGetSymbolAddress((void**)&nh,   g_nh);
    cudaGetSymbolAddress((void**)&nl,   g_nl);
    cudaGetSymbolAddress((void**)&wsw,  g_Wsw);

    cudaFuncSetAttribute(k_mma, cudaFuncAttributeMaxDynamicSharedMemorySize,
                         SMEM_TOTAL);

    const int TB = 256;
    k_wconv  <<<(2 * 2 * 128 * 128 + TB - 1) / TB, TB>>>(W);
    k_esplit <<<(N_NODES * DIM4 + TB - 1) / TB, TB>>>(entity);
    k_zero   <<<(N_NODES + TB - 1) / TB, TB>>>();
    k_count  <<<(N_EDGES + TB - 1) / TB, TB>>>(edst);
    k_scan1  <<<SCAN_G, SCAN_B>>>();
    k_scan2  <<<1, 64>>>();
    k_scan3  <<<SCAN_G, SCAN_B>>>();
    k_scatter<<<(N_EDGES + TB - 1) / TB, TB>>>(edst, enbr, erel);

    const int agrid = (N_NODES + 7) / 8;
    const int ggrid = (N_NODES + 127) / 128;

    // layer 0: attn on entity; mma writes prev (fp32) + next A split (bf16)
    k_attn<<<agrid, TB>>>(entity, entity, relation);
    k_mma <<<ggrid, TB, SMEM_TOTAL>>>(ah, al, nh, nl, wsw + 0 * 2 * 65536,
                                      b + 0 * DIM, entity, prev, ah, al);
    // layer 1: attn on prev; mma writes final out
    k_attn<<<agrid, TB>>>(prev, entity, relation);
    k_mma <<<ggrid, TB, SMEM_TOTAL>>>(ah, al, nh, nl, wsw + 1 * 2 * 65536,
                                      b + 1 * DIM, entity, out,
                                      (__nv_bfloat16*)nullptr,
                                      (__nv_bfloat16*)nullptr);
}

// round 8
// speedup vs baseline: 1.0813x; 1.0813x over previous
#include <cuda_runtime.h>
#include <cuda_bf16.h>
#include <math_constants.h>
#include <cstdint>
#include <mma.h>

using namespace nvcuda;

#define N_NODES 50000
#define N_EDGES 600000
#define N_REL   64
#define DIM     128
#define DIM4    32

#define SCAN_B 1024
#define SCAN_G ((N_NODES + SCAN_B - 1) / SCAN_B)   // 49

typedef unsigned long long ull;

// ---------------- device scratch (no allocations allowed) ----------------
__device__ float g_prev[N_NODES * DIM];
__device__ float g_neigh[N_NODES * DIM];
__device__ int   g_deg[N_NODES];
__device__ int   g_cursor[N_NODES];
__device__ int   g_rowptr[N_NODES + 1];
__device__ int   g_part[SCAN_G];
__device__ int   g_nbr[N_EDGES];
__device__ int   g_rel[N_EDGES];
// W split: [layer][k-chunk] -> 64KB blob: 32KB hi (128x128 bf16 [k][n]) + 32KB lo
__device__ __align__(16) unsigned char g_Wsw[2][2][65536];

__device__ __forceinline__ float tanh_fast(float x) {
    float y; asm("tanh.approx.f32 %0, %1;" : "=f"(y) : "f"(x)); return y;
}

// ---------------- CSR build ----------------
__global__ void k_zero()
{
    int i = blockIdx.x * blockDim.x + threadIdx.x;
    if (i < N_NODES) { g_deg[i] = 0; g_cursor[i] = 0; }
}
__global__ void k_count(const int* __restrict__ dst)
{
    int e = blockIdx.x * blockDim.x + threadIdx.x;
    if (e < N_EDGES) atomicAdd(&g_deg[dst[e]], 1);
}
__global__ void k_scan1()
{
    __shared__ int warpsum[32];
    const int lane = threadIdx.x & 31;
    const int wid  = threadIdx.x >> 5;
    const int i    = blockIdx.x * SCAN_B + threadIdx.x;

    int v = (i < N_NODES) ? g_deg[i] : 0;
    int s = v;
    #pragma unroll
    for (int o = 1; o < 32; o <<= 1) {
        int u = __shfl_up_sync(0xffffffffu, s, o);
        if (lane >= o) s += u;
    }
    if (lane == 31) warpsum[wid] = s;
    __syncthreads();
    if (wid == 0) {
        int ws = warpsum[lane];
        #pragma unroll
        for (int o = 1; o < 32; o <<= 1) {
            int u = __shfl_up_sync(0xffffffffu, ws, o);
            if (lane >= o) ws += u;
        }
        warpsum[lane] = ws;
    }
    __syncthreads();
    int incl = s + (wid ? warpsum[wid - 1] : 0);
    if (i < N_NODES) g_rowptr[i] = incl - v;
    if (threadIdx.x == SCAN_B - 1) g_part[blockIdx.x] = incl;
}
__global__ void k_scan2()
{
    __shared__ int sp[64];
    const int t = threadIdx.x;
    sp[t] = (t < SCAN_G) ? g_part[t] : 0;
    __syncthreads();
    #pragma unroll
    for (int o = 1; o < 64; o <<= 1) {
        int u = (t >= o) ? sp[t - o] : 0;
        __syncthreads();
        sp[t] += u;
        __syncthreads();
    }
    if (t < SCAN_G) g_part[t] = (t == 0) ? 0 : sp[t - 1];
    if (t == 63) g_rowptr[N_NODES] = sp[SCAN_G - 1];
}
__global__ void k_scan3()
{
    int i = blockIdx.x * SCAN_B + threadIdx.x;
    if (i < N_NODES) g_rowptr[i] += g_part[blockIdx.x];
}
__global__ void k_scatter(const int* __restrict__ dst,
                          const int* __restrict__ nbr,
                          const int* __restrict__ rel)
{
    int e = blockIdx.x * blockDim.x + threadIdx.x;
    if (e < N_EDGES) {
        int d   = dst[e];
        int pos = g_rowptr[d] + atomicAdd(&g_cursor[d], 1);
        g_nbr[pos] = nbr[e];
        g_rel[pos] = rel[e];
    }
}

// ---------------- W bf16 hi/lo split (once). blob[kc]: hi[k][n], lo[k][n] ----
__global__ void k_wconv(const float* __restrict__ W)
{
    int idx = blockIdx.x * blockDim.x + threadIdx.x;  // 65536
    if (idx >= 2 * 2 * 128 * 128) return;
    int l  = idx >> 15;
    int r  = idx & 32767;
    int kc = r >> 14; r &= 16383;
    int k  = r >> 7;
    int n  = r & 127;
    float w = W[(l * 256 + kc * 128 + k) * 128 + n];
    __nv_bfloat16 hi = __float2bfloat16(w);
    __nv_bfloat16 lo = __float2bfloat16(w - __bfloat162float(hi));
    __nv_bfloat16* base = (__nv_bfloat16*)&g_Wsw[l][kc][0];
    base[k * 128 + n]         = hi;
    base[16384 + k * 128 + n] = lo;
}

// ---------------- attention: one warp per node ----------------
// No max-subtraction (|score| <= ~7 by Cauchy-Schwarz -> exp safe in fp32).
// 4x edge unroll: 4 independent shfl-reduction chains overlap their latency.
__global__ void __launch_bounds__(256)
k_attn(const float* __restrict__ in,
       const float* __restrict__ entity,
       const float* __restrict__ relation)
{
    const int wid  = threadIdx.x >> 5;
    const int lane = threadIdx.x & 31;
    const int node = blockIdx.x * 8 + wid;
    if (node >= N_NODES) return;

    const int start = g_rowptr[node];
    const int end   = g_rowptr[node + 1];
    if (start == end) return;                         // epilogue handles deg==0

    const float4* ent4 = (const float4*)entity;
    const float4* in4  = (const float4*)in;
    const float4* rel4 = (const float4*)relation;
    float4*       ng4  = (float4*)g_neigh;

    float4 ed = ent4[node * DIM4 + lane];

    float  dsum = 0.f;
    float4 acc  = make_float4(0.f, 0.f, 0.f, 0.f);

    for (int base = start; base < end; base += 4) {
        float4 x[4];
        float  s[4];
        // gather + partial dots (independent, high MLP)
        #pragma unroll
        for (int i = 0; i < 4; ++i) {
            if (base + i < end) {
                int nb = g_nbr[base + i];
                int rl = g_rel[base + i];
                x[i] = in4[nb * DIM4 + lane];
                float4 r = rel4[rl * DIM4 + lane];
                float qx = tanh_fast(ed.x + r.x);
                float qy = tanh_fast(ed.y + r.y);
                float qz = tanh_fast(ed.z + r.z);
                float qw = tanh_fast(ed.w + r.w);
                s[i] = x[i].x * qx + x[i].y * qy + x[i].z * qz + x[i].w * qw;
            } else {
                x[i] = make_float4(0.f, 0.f, 0.f, 0.f);
                s[i] = -100.f;                   // exp(32*-100) == 0
            }
        }
        // 4 independent butterfly reductions — latencies overlap
        #pragma unroll
        for (int off = 16; off; off >>= 1) {
            #pragma unroll
            for (int i = 0; i < 4; ++i)
                s[i] += __shfl_xor_sync(0xffffffffu, s[i], off);
        }
        // accumulate (cheap FMA tail)
        #pragma unroll
        for (int i = 0; i < 4; ++i) {
            float w = __expf(s[i]);
            dsum += w;
            acc.x += w * x[i].x; acc.y += w * x[i].y;
            acc.z += w * x[i].z; acc.w += w * x[i].w;
        }
    }

    const float inv = 1.0f / dsum;
    ng4[node * DIM4 + lane] = make_float4(acc.x * inv, acc.y * inv,
                                          acc.z * inv, acc.w * inv);
}

// ---------------- WMMA bf16x3 GEMM + epilogue (R5 structure) ----------------
#define AS_STRIDE 136                       // bf16 elems per row (pad 8)
#define CS_STRIDE 132                       // f32 elems per row (pad 4)
#define SM_BIAS   0
#define SM_A_HI   1024
#define SM_A_LO   (SM_A_HI + 128 * AS_STRIDE * 2)
#define SM_B_HI   (SM_A_LO + 128 * AS_STRIDE * 2)
#define SM_B_LO   (SM_B_HI + 128 * AS_STRIDE * 2)
#define SM_C      1024
#define SMEM_TOTAL (SM_B_LO + 128 * AS_STRIDE * 2)   // 140288

__global__ void __launch_bounds__(256, 1)
k_mma(const float* __restrict__ in,
      const float* __restrict__ neigh,
      const unsigned char* __restrict__ wsw,
      const float* __restrict__ bl,
      const float* __restrict__ entity,
      float*       __restrict__ out)
{
    extern __shared__ unsigned char smem[];
    const int t      = threadIdx.x;
    const int wid    = t >> 5;
    const int warp_m = wid >> 2;
    const int warp_n = wid & 3;
    const int m0     = blockIdx.x * 128;

    float* sbias = (float*)(smem + SM_BIAS);
    if (t < 128) sbias[t] = bl[t];

    __nv_bfloat16* Ah = (__nv_bfloat16*)(smem + SM_A_HI);
    __nv_bfloat16* Al = (__nv_bfloat16*)(smem + SM_A_LO);
    __nv_bfloat16* Bh = (__nv_bfloat16*)(smem + SM_B_HI);
    __nv_bfloat16* Bl = (__nv_bfloat16*)(smem + SM_B_LO);

    wmma::fragment<wmma::accumulator, 16, 16, 16, float> c[4][2];
    #pragma unroll
    for (int mt = 0; mt < 4; ++mt)
        #pragma unroll
        for (int nt = 0; nt < 2; ++nt)
            wmma::fill_fragment(c[mt][nt], 0.f);

    for (int kc = 0; kc < 2; ++kc) {
        const float* Asrc = kc ? neigh : in;
        __syncthreads();

        // A chunk [128 x 128] fp32 -> bf16 hi/lo into padded smem
        #pragma unroll
        for (int p = 0; p < 16; ++p) {
            int f   = p * 256 + t;
            int row = f >> 5;
            int c4  = f & 31;
            int node = m0 + row;
            float4 v = make_float4(0.f, 0.f, 0.f, 0.f);
            if (node < N_NODES)
                v = *(const float4*)(Asrc + node * DIM + c4 * 4);

            __nv_bfloat16 h0 = __float2bfloat16(v.x);
            __nv_bfloat16 h1 = __float2bfloat16(v.y);
            __nv_bfloat16 h2 = __float2bfloat16(v.z);
            __nv_bfloat16 h3 = __float2bfloat16(v.w);
            __nv_bfloat16 l0 = __float2bfloat16(v.x - __bfloat162float(h0));
            __nv_bfloat16 l1 = __float2bfloat16(v.y - __bfloat162float(h1));
            __nv_bfloat16 l2 = __float2bfloat16(v.z - __bfloat162float(h2));
            __nv_bfloat16 l3 = __float2bfloat16(v.w - __bfloat162float(h3));

            ull ph = (ull)__bfloat16_as_ushort(h0)
                   | ((ull)__bfloat16_as_ushort(h1) << 16)
                   | ((ull)__bfloat16_as_ushort(h2) << 32)
                   | ((ull)__bfloat16_as_ushort(h3) << 48);
            ull pl = (ull)__bfloat16_as_ushort(l0)
                   | ((ull)__bfloat16_as_ushort(l1) << 16)
                   | ((ull)__bfloat16_as_ushort(l2) << 32)
                   | ((ull)__bfloat16_as_ushort(l3) << 48);

            int eo = row * AS_STRIDE + c4 * 4;
            *(ull*)(Ah + eo) = ph;
            *(ull*)(Al + eo) = pl;
        }
        // B tiles: copy pre-split W blob into padded smem
        {
            const uint32_t* sh = (const uint32_t*)(wsw + kc * 65536);
            const uint32_t* sl = (const uint32_t*)(wsw + kc * 65536 + 32768);
            #pragma unroll
            for (int p = 0; p < 32; ++p) {
                int idx = p * 256 + t;
                int row = idx >> 6;
                int cp  = idx & 63;
                int eo  = row * AS_STRIDE + cp * 2;
                *(uint32_t*)(Bh + eo) = sh[idx];
                *(uint32_t*)(Bl + eo) = sl[idx];
            }
        }
        __syncthreads();

        #pragma unroll
        for (int ks = 0; ks < 8; ++ks) {
            wmma::fragment<wmma::matrix_b, 16, 16, 16, __nv_bfloat16,
                           wmma::row_major> bh[2], blo[2];
            #pragma unroll
            for (int nt = 0; nt < 2; ++nt) {
                int ncol = warp_n * 32 + nt * 16;
                wmma::load_matrix_sync(bh[nt],  Bh + ks * 16 * AS_STRIDE + ncol,
                                       AS_STRIDE);
                wmma::load_matrix_sync(blo[nt], Bl + ks * 16 * AS_STRIDE + ncol,
                                       AS_STRIDE);
            }
            #pragma unroll
            for (int mt = 0; mt < 4; ++mt) {
                int mrow = warp_m * 64 + mt * 16;
                wmma::fragment<wmma::matrix_a, 16, 16, 16, __nv_bfloat16,
                               wmma::row_major> ah, alo;
                wmma::load_matrix_sync(ah,  Ah + mrow * AS_STRIDE + ks * 16,
                                       AS_STRIDE);
                wmma::load_matrix_sync(alo, Al + mrow * AS_STRIDE + ks * 16,
                                       AS_STRIDE);
                #pragma unroll
                for (int nt = 0; nt < 2; ++nt) {
                    wmma::mma_sync(c[mt][nt], ah,  bh[nt],  c[mt][nt]);
                    wmma::mma_sync(c[mt][nt], ah,  blo[nt], c[mt][nt]);
                    wmma::mma_sync(c[mt][nt], alo, bh[nt],  c[mt][nt]);
                }
            }
        }
    }
    __syncthreads();

    float* Cs = (float*)(smem + SM_C);
    #pragma unroll
    for (int mt = 0; mt < 4; ++mt)
        #pragma unroll
        for (int nt = 0; nt < 2; ++nt)
            wmma::store_matrix_sync(Cs + (warp_m * 64 + mt * 16) * CS_STRIDE
                                       + warp_n * 32 + nt * 16,
                                    c[mt][nt], CS_STRIDE, wmma::mem_row_major);
    __syncthreads();

    // epilogue: 2 threads per row (64 cols each): bias + leaky + L2 norm
    {
        const int r    = t >> 1;
        const int half = t & 1;
        const int node = m0 + r;
        const float* crow = Cs + r * CS_STRIDE + half * 64;
        const float* brow = sbias + half * 64;

        float sq = 0.f;
        #pragma unroll
        for (int j = 0; j < 64; ++j) {
            float v = crow[j] + brow[j];
            v = (v > 0.f) ? v : 0.01f * v;
            sq += v * v;
        }
        sq += __shfl_xor_sync(0xffffffffu, sq, 1);
        float rn = rsqrtf(sq);

        if (node < N_NODES) {
            int deg = g_rowptr[node + 1] - g_rowptr[node];
            float4*       out4 = (float4*)out;
            const float4* ent4 = (const float4*)entity;
            #pragma unroll
            for (int j4 = 0; j4 < 16; ++j4) {
                float4 o;
                if (deg == 0) {
                    o = ent4[node * DIM4 + half * 16 + j4];
                } else {
                    float v0 = crow[j4 * 4 + 0] + brow[j4 * 4 + 0];
                    float v1 = crow[j4 * 4 + 1] + brow[j4 * 4 + 1];
                    float v2 = crow[j4 * 4 + 2] + brow[j4 * 4 + 2];
                    float v3 = crow[j4 * 4 + 3] + brow[j4 * 4 + 3];
                    o.x = ((v0 > 0.f) ? v0 : 0.01f * v0) * rn;
                    o.y = ((v1 > 0.f) ? v1 : 0.01f * v1) * rn;
                    o.z = ((v2 > 0.f) ? v2 : 0.01f * v2) * rn;
                    o.w = ((v3 > 0.f) ? v3 : 0.01f * v3) * rn;
                }
                out4[node * DIM4 + half * 16 + j4] = o;
            }
        }
    }
}

// ---------------- launch ----------------
extern "C" void kernel_launch(void* const* d_in, const int* in_sizes, int n_in,
                              void* d_out, int out_size)
{
    const float* entity   = (const float*)d_in[0];
    const float* relation = (const float*)d_in[1];
    const float* W        = (const float*)d_in[2];
    const float* b        = (const float*)d_in[3];
    const int*   edst     = (const int*)d_in[4];
    const int*   enbr     = (const int*)d_in[5];
    const int*   erel     = (const int*)d_in[6];
    float*       out      = (float*)d_out;

    float* prev  = nullptr;
    float* neigh = nullptr;
    unsigned char* wsw = nullptr;
    cudaGetSymbolAddress((void**)&prev,  g_prev);
    cudaGetSymbolAddress((void**)&neigh, g_neigh);
    cudaGetSymbolAddress((void**)&wsw,   g_Wsw);

    cudaFuncSetAttribute(k_mma, cudaFuncAttributeMaxDynamicSharedMemorySize,
                         SMEM_TOTAL);

    const int TB = 256;
    k_wconv  <<<(2 * 2 * 128 * 128 + TB - 1) / TB, TB>>>(W);
    k_zero   <<<(N_NODES + TB - 1) / TB, TB>>>();
    k_count  <<<(N_EDGES + TB - 1) / TB, TB>>>(edst);
    k_scan1  <<<SCAN_G, SCAN_B>>>();
    k_scan2  <<<1, 64>>>();
    k_scan3  <<<SCAN_G, SCAN_B>>>();
    k_scatter<<<(N_EDGES + TB - 1) / TB, TB>>>(edst, enbr, erel);

    const int agrid = (N_NODES + 7) / 8;
    const int ggrid = (N_NODES + 127) / 128;

    // layer 0
    k_attn<<<agrid, TB>>>(entity, entity, relation);
    k_mma <<<ggrid, TB, SMEM_TOTAL>>>(entity, neigh, wsw + 0 * 2 * 65536,
                                      b + 0 * DIM, entity, prev);
    // layer 1
    k_attn<<<agrid, TB>>>(prev, entity, relation);
    k_mma <<<ggrid, TB, SMEM_TOTAL>>>(prev, neigh, wsw + 1 * 2 * 65536,
                                      b + 1 * DIM, entity, out);
}

// round 9
// speedup vs baseline: 1.1651x; 1.0774x over previous
#include <cuda_runtime.h>
#include <cuda_bf16.h>
#include <math_constants.h>
#include <cstdint>
#include <mma.h>

using namespace nvcuda;

#define N_NODES 50000
#define N_EDGES 600000
#define N_REL   64
#define DIM     128
#define DIM4    32

#define SCAN_B 1024
#define SCAN_G ((N_NODES + SCAN_B - 1) / SCAN_B)   // 49

typedef unsigned long long ull;

// ---------------- device scratch (no allocations allowed) ----------------
// NOTE: device globals are zero-initialized at module load; k_reset at the
// END of each graph replay re-zeroes them for the next replay (deterministic).
__device__ float g_prev[N_NODES * DIM];
__device__ float g_neigh[N_NODES * DIM];
__device__ int   g_deg[N_NODES];
__device__ int   g_cursor[N_NODES];
__device__ int   g_rowptr[N_NODES + 1];
__device__ ull   g_psync[SCAN_G];               // scan lookback: bit63 flag | sum
__device__ ull   g_edge[N_EDGES];               // packed (rel << 32) | nbr
// W split: [layer][k-chunk] -> 64KB blob: 32KB hi (128x128 bf16 [k][n]) + 32KB lo
__device__ __align__(16) unsigned char g_Wsw[2][2][65536];

__device__ __forceinline__ float tanh_fast(float x) {
    float y; asm("tanh.approx.f32 %0, %1;" : "=f"(y) : "f"(x)); return y;
}

// ---------------- CSR build ----------------
__global__ void k_count(const int* __restrict__ dst)
{
    int e = blockIdx.x * blockDim.x + threadIdx.x;
    if (e < N_EDGES) atomicAdd(&g_deg[dst[e]], 1);
}

// single-launch scan: block-local scan + decoupled lookback over 49 partials.
// All 49 blocks are co-resident (grid < #SMs) so spinning is deadlock-free.
__global__ void k_scan()
{
    __shared__ int warpsum[32];
    __shared__ int s_prefix;
    const int lane = threadIdx.x & 31;
    const int wid  = threadIdx.x >> 5;
    const int b    = blockIdx.x;
    const int i    = b * SCAN_B + threadIdx.x;

    int v = (i < N_NODES) ? g_deg[i] : 0;
    int s = v;
    #pragma unroll
    for (int o = 1; o < 32; o <<= 1) {
        int u = __shfl_up_sync(0xffffffffu, s, o);
        if (lane >= o) s += u;
    }
    if (lane == 31) warpsum[wid] = s;
    __syncthreads();
    if (wid == 0) {
        int ws = warpsum[lane];
        #pragma unroll
        for (int o = 1; o < 32; o <<= 1) {
            int u = __shfl_up_sync(0xffffffffu, ws, o);
            if (lane >= o) ws += u;
        }
        warpsum[lane] = ws;
    }
    __syncthreads();
    const int incl = s + (wid ? warpsum[wid - 1] : 0);

    // publish this block's total (value+flag in one 64-bit word)
    if (threadIdx.x == SCAN_B - 1)
        atomicExch(&g_psync[b], (1ull << 63) | (ull)(unsigned)incl);

    // lookback: warp 0 sums totals of blocks 0..b-1
    if (wid == 0) {
        int pre = 0;
        for (int pb = lane; pb < b; pb += 32) {
            ull w;
            do { w = atomicAdd(&g_psync[pb], 0ull); } while (!(w >> 63));
            pre += (int)(w & 0x7fffffffu);
        }
        #pragma unroll
        for (int o = 16; o; o >>= 1)
            pre += __shfl_xor_sync(0xffffffffu, pre, o);
        if (lane == 0) s_prefix = pre;
    }
    __syncthreads();

    if (i < N_NODES) g_rowptr[i] = incl - v + s_prefix;
    if (b == SCAN_G - 1 && threadIdx.x == SCAN_B - 1)
        g_rowptr[N_NODES] = incl + s_prefix;
}

__global__ void k_scatter(const int* __restrict__ dst,
                          const int* __restrict__ nbr,
                          const int* __restrict__ rel)
{
    int e = blockIdx.x * blockDim.x + threadIdx.x;
    if (e < N_EDGES) {
        int d   = dst[e];
        int pos = g_rowptr[d] + atomicAdd(&g_cursor[d], 1);
        g_edge[pos] = ((ull)(unsigned)rel[e] << 32) | (unsigned)nbr[e];
    }
}

// trailing reset: re-zero scratch for the NEXT graph replay
__global__ void k_reset()
{
    int i = blockIdx.x * blockDim.x + threadIdx.x;
    if (i < N_NODES) { g_deg[i] = 0; g_cursor[i] = 0; }
    if (i < SCAN_G) g_psync[i] = 0ull;
}

// ---------------- W bf16 hi/lo split (once). blob[kc]: hi[k][n], lo[k][n] ----
__global__ void k_wconv(const float* __restrict__ W)
{
    int idx = blockIdx.x * blockDim.x + threadIdx.x;  // 65536
    if (idx >= 2 * 2 * 128 * 128) return;
    int l  = idx >> 15;
    int r  = idx & 32767;
    int kc = r >> 14; r &= 16383;
    int k  = r >> 7;
    int n  = r & 127;
    float w = W[(l * 256 + kc * 128 + k) * 128 + n];
    __nv_bfloat16 hi = __float2bfloat16(w);
    __nv_bfloat16 lo = __float2bfloat16(w - __bfloat162float(hi));
    __nv_bfloat16* base = (__nv_bfloat16*)&g_Wsw[l][kc][0];
    base[k * 128 + n]         = hi;
    base[16384 + k * 128 + n] = lo;
}

// ---------------- attention: one warp per node ----------------
// No max-subtraction (|score| small by Cauchy-Schwarz -> exp safe in fp32).
// 4x edge unroll: 4 independent shfl-reduction chains overlap their latency.
__global__ void __launch_bounds__(256)
k_attn(const float* __restrict__ in,
       const float* __restrict__ entity,
       const float* __restrict__ relation)
{
    const int wid  = threadIdx.x >> 5;
    const int lane = threadIdx.x & 31;
    const int node = blockIdx.x * 8 + wid;
    if (node >= N_NODES) return;

    const int start = g_rowptr[node];
    const int end   = g_rowptr[node + 1];
    if (start == end) return;                         // epilogue handles deg==0

    const float4* ent4 = (const float4*)entity;
    const float4* in4  = (const float4*)in;
    const float4* rel4 = (const float4*)relation;
    float4*       ng4  = (float4*)g_neigh;

    float4 ed = ent4[node * DIM4 + lane];

    float  dsum = 0.f;
    float4 acc  = make_float4(0.f, 0.f, 0.f, 0.f);

    for (int base = start; base < end; base += 4) {
        float4 x[4];
        float  s[4];
        #pragma unroll
        for (int i = 0; i < 4; ++i) {
            if (base + i < end) {
                ull ev = g_edge[base + i];
                int nb = (int)(ev & 0xffffffffu);
                int rl = (int)(ev >> 32);
                x[i] = in4[nb * DIM4 + lane];
                float4 r = rel4[rl * DIM4 + lane];
                float qx = tanh_fast(ed.x + r.x);
                float qy = tanh_fast(ed.y + r.y);
                float qz = tanh_fast(ed.z + r.z);
                float qw = tanh_fast(ed.w + r.w);
                s[i] = x[i].x * qx + x[i].y * qy + x[i].z * qz + x[i].w * qw;
            } else {
                x[i] = make_float4(0.f, 0.f, 0.f, 0.f);
                s[i] = -100.f;                   // exp(32*-100) == 0
            }
        }
        #pragma unroll
        for (int off = 16; off; off >>= 1) {
            #pragma unroll
            for (int i = 0; i < 4; ++i)
                s[i] += __shfl_xor_sync(0xffffffffu, s[i], off);
        }
        #pragma unroll
        for (int i = 0; i < 4; ++i) {
            float w = __expf(s[i]);
            dsum += w;
            acc.x += w * x[i].x; acc.y += w * x[i].y;
            acc.z += w * x[i].z; acc.w += w * x[i].w;
        }
    }

    const float inv = 1.0f / dsum;
    ng4[node * DIM4 + lane] = make_float4(acc.x * inv, acc.y * inv,
                                          acc.z * inv, acc.w * inv);
}

// ---------------- WMMA bf16x3 GEMM + epilogue (unchanged, measured-best) ----
#define AS_STRIDE 136                       // bf16 elems per row (pad 8)
#define CS_STRIDE 132                       // f32 elems per row (pad 4)
#define SM_BIAS   0
#define SM_A_HI   1024
#define SM_A_LO   (SM_A_HI + 128 * AS_STRIDE * 2)
#define SM_B_HI   (SM_A_LO + 128 * AS_STRIDE * 2)
#define SM_B_LO   (SM_B_HI + 128 * AS_STRIDE * 2)
#define SM_C      1024
#define SMEM_TOTAL (SM_B_LO + 128 * AS_STRIDE * 2)   // 140288

__global__ void __launch_bounds__(256, 1)
k_mma(const float* __restrict__ in,
      const float* __restrict__ neigh,
      const unsigned char* __restrict__ wsw,
      const float* __restrict__ bl,
      const float* __restrict__ entity,
      float*       __restrict__ out)
{
    extern __shared__ unsigned char smem[];
    const int t      = threadIdx.x;
    const int wid    = t >> 5;
    const int warp_m = wid >> 2;
    const int warp_n = wid & 3;
    const int m0     = blockIdx.x * 128;

    float* sbias = (float*)(smem + SM_BIAS);
    if (t < 128) sbias[t] = bl[t];

    __nv_bfloat16* Ah = (__nv_bfloat16*)(smem + SM_A_HI);
    __nv_bfloat16* Al = (__nv_bfloat16*)(smem + SM_A_LO);
    __nv_bfloat16* Bh = (__nv_bfloat16*)(smem + SM_B_HI);
    __nv_bfloat16* Bl = (__nv_bfloat16*)(smem + SM_B_LO);

    wmma::fragment<wmma::accumulator, 16, 16, 16, float> c[4][2];
    #pragma unroll
    for (int mt = 0; mt < 4; ++mt)
        #pragma unroll
        for (int nt = 0; nt < 2; ++nt)
            wmma::fill_fragment(c[mt][nt], 0.f);

    for (int kc = 0; kc < 2; ++kc) {
        const float* Asrc = kc ? neigh : in;
        __syncthreads();

        // A chunk [128 x 128] fp32 -> bf16 hi/lo into padded smem
        #pragma unroll
        for (int p = 0; p < 16; ++p) {
            int f   = p * 256 + t;
            int row = f >> 5;
            int c4  = f & 31;
            int node = m0 + row;
            float4 v = make_float4(0.f, 0.f, 0.f, 0.f);
            if (node < N_NODES)
                v = *(const float4*)(Asrc + node * DIM + c4 * 4);

            __nv_bfloat16 h0 = __float2bfloat16(v.x);
            __nv_bfloat16 h1 = __float2bfloat16(v.y);
            __nv_bfloat16 h2 = __float2bfloat16(v.z);
            __nv_bfloat16 h3 = __float2bfloat16(v.w);
            __nv_bfloat16 l0 = __float2bfloat16(v.x - __bfloat162float(h0));
            __nv_bfloat16 l1 = __float2bfloat16(v.y - __bfloat162float(h1));
            __nv_bfloat16 l2 = __float2bfloat16(v.z - __bfloat162float(h2));
            __nv_bfloat16 l3 = __float2bfloat16(v.w - __bfloat162float(h3));

            ull ph = (ull)__bfloat16_as_ushort(h0)
                   | ((ull)__bfloat16_as_ushort(h1) << 16)
                   | ((ull)__bfloat16_as_ushort(h2) << 32)
                   | ((ull)__bfloat16_as_ushort(h3) << 48);
            ull pl = (ull)__bfloat16_as_ushort(l0)
                   | ((ull)__bfloat16_as_ushort(l1) << 16)
                   | ((ull)__bfloat16_as_ushort(l2) << 32)
                   | ((ull)__bfloat16_as_ushort(l3) << 48);

            int eo = row * AS_STRIDE + c4 * 4;
            *(ull*)(Ah + eo) = ph;
            *(ull*)(Al + eo) = pl;
        }
        // B tiles: copy pre-split W blob into padded smem
        {
            const uint32_t* sh = (const uint32_t*)(wsw + kc * 65536);
            const uint32_t* sl = (const uint32_t*)(wsw + kc * 65536 + 32768);
            #pragma unroll
            for (int p = 0; p < 32; ++p) {
                int idx = p * 256 + t;
                int row = idx >> 6;
                int cp  = idx & 63;
                int eo  = row * AS_STRIDE + cp * 2;
                *(uint32_t*)(Bh + eo) = sh[idx];
                *(uint32_t*)(Bl + eo) = sl[idx];
            }
        }
        __syncthreads();

        #pragma unroll
        for (int ks = 0; ks < 8; ++ks) {
            wmma::fragment<wmma::matrix_b, 16, 16, 16, __nv_bfloat16,
                           wmma::row_major> bh[2], blo[2];
            #pragma unroll
            for (int nt = 0; nt < 2; ++nt) {
                int ncol = warp_n * 32 + nt * 16;
                wmma::load_matrix_sync(bh[nt],  Bh + ks * 16 * AS_STRIDE + ncol,
                                       AS_STRIDE);
                wmma::load_matrix_sync(blo[nt], Bl + ks * 16 * AS_STRIDE + ncol,
                                       AS_STRIDE);
            }
            #pragma unroll
            for (int mt = 0; mt < 4; ++mt) {
                int mrow = warp_m * 64 + mt * 16;
                wmma::fragment<wmma::matrix_a, 16, 16, 16, __nv_bfloat16,
                               wmma::row_major> ah, alo;
                wmma::load_matrix_sync(ah,  Ah + mrow * AS_STRIDE + ks * 16,
                                       AS_STRIDE);
                wmma::load_matrix_sync(alo, Al + mrow * AS_STRIDE + ks * 16,
                                       AS_STRIDE);
                #pragma unroll
                for (int nt = 0; nt < 2; ++nt) {
                    wmma::mma_sync(c[mt][nt], ah,  bh[nt],  c[mt][nt]);
                    wmma::mma_sync(c[mt][nt], ah,  blo[nt], c[mt][nt]);
                    wmma::mma_sync(c[mt][nt], alo, bh[nt],  c[mt][nt]);
                }
            }
        }
    }
    __syncthreads();

    float* Cs = (float*)(smem + SM_C);
    #pragma unroll
    for (int mt = 0; mt < 4; ++mt)
        #pragma unroll
        for (int nt = 0; nt < 2; ++nt)
            wmma::store_matrix_sync(Cs + (warp_m * 64 + mt * 16) * CS_STRIDE
                                       + warp_n * 32 + nt * 16,
                                    c[mt][nt], CS_STRIDE, wmma::mem_row_major);
    __syncthreads();

    // epilogue: 2 threads per row (64 cols each): bias + leaky + L2 norm
    {
        const int r    = t >> 1;
        const int half = t & 1;
        const int node = m0 + r;
        const float* crow = Cs + r * CS_STRIDE + half * 64;
        const float* brow = sbias + half * 64;

        float sq = 0.f;
        #pragma unroll
        for (int j = 0; j < 64; ++j) {
            float v = crow[j] + brow[j];
            v = (v > 0.f) ? v : 0.01f * v;
            sq += v * v;
        }
        sq += __shfl_xor_sync(0xffffffffu, sq, 1);
        float rn = rsqrtf(sq);

        if (node < N_NODES) {
            int deg = g_rowptr[node + 1] - g_rowptr[node];
            float4*       out4 = (float4*)out;
            const float4* ent4 = (const float4*)entity;
            #pragma unroll
            for (int j4 = 0; j4 < 16; ++j4) {
                float4 o;
                if (deg == 0) {
                    o = ent4[node * DIM4 + half * 16 + j4];
                } else {
                    float v0 = crow[j4 * 4 + 0] + brow[j4 * 4 + 0];
                    float v1 = crow[j4 * 4 + 1] + brow[j4 * 4 + 1];
                    float v2 = crow[j4 * 4 + 2] + brow[j4 * 4 + 2];
                    float v3 = crow[j4 * 4 + 3] + brow[j4 * 4 + 3];
                    o.x = ((v0 > 0.f) ? v0 : 0.01f * v0) * rn;
                    o.y = ((v1 > 0.f) ? v1 : 0.01f * v1) * rn;
                    o.z = ((v2 > 0.f) ? v2 : 0.01f * v2) * rn;
                    o.w = ((v3 > 0.f) ? v3 : 0.01f * v3) * rn;
                }
                out4[node * DIM4 + half * 16 + j4] = o;
            }
        }
    }
}

// ---------------- launch ----------------
extern "C" void kernel_launch(void* const* d_in, const int* in_sizes, int n_in,
                              void* d_out, int out_size)
{
    const float* entity   = (const float*)d_in[0];
    const float* relation = (const float*)d_in[1];
    const float* W        = (const float*)d_in[2];
    const float* b        = (const float*)d_in[3];
    const int*   edst     = (const int*)d_in[4];
    const int*   enbr     = (const int*)d_in[5];
    const int*   erel     = (const int*)d_in[6];
    float*       out      = (float*)d_out;

    float* prev  = nullptr;
    float* neigh = nullptr;
    unsigned char* wsw = nullptr;
    cudaGetSymbolAddress((void**)&prev,  g_prev);
    cudaGetSymbolAddress((void**)&neigh, g_neigh);
    cudaGetSymbolAddress((void**)&wsw,   g_Wsw);

    cudaFuncSetAttribute(k_mma, cudaFuncAttributeMaxDynamicSharedMemorySize,
                         SMEM_TOTAL);

    const int TB = 256;
    const int agrid = (N_NODES + 7) / 8;
    const int ggrid = (N_NODES + 127) / 128;

    // deg/cursor/psync are zero on entry (zero-init on load, k_reset on replay)
    k_count  <<<(N_EDGES + TB - 1) / TB, TB>>>(edst);              // #1
    k_scan   <<<SCAN_G, SCAN_B>>>();                               // #2
    k_scatter<<<(N_EDGES + TB - 1) / TB, TB>>>(edst, enbr, erel);  // #3
    // layer 0
    k_attn<<<agrid, TB>>>(entity, entity, relation);               // #4 (profiled)
    k_wconv<<<(2 * 2 * 128 * 128 + TB - 1) / TB, TB>>>(W);         // #5
    k_mma <<<ggrid, TB, SMEM_TOTAL>>>(entity, neigh, wsw + 0 * 2 * 65536,
                                      b + 0 * DIM, entity, prev);  // #6
    // layer 1
    k_attn<<<agrid, TB>>>(prev, entity, relation);                 // #7
    k_mma <<<ggrid, TB, SMEM_TOTAL>>>(prev, neigh, wsw + 1 * 2 * 65536,
                                      b + 1 * DIM, entity, out);   // #8
    // reset scratch for next replay
    k_reset<<<(N_NODES + TB - 1) / TB, TB>>>();                    // #9
}